// round 12
// baseline (speedup 1.0000x reference)
#include <cuda_runtime.h>
#include <math.h>
#include <stdint.h>

#define BB 128
#define RR 4096
#define DD 256
#define NROW (BB * RR)

// Static device scratch (no allocations allowed). g_cnt is zero-initialized
// at load and self-resetting (tail kernel resets it each run).
__device__ int g_cnt[BB];

// ---------------------------------------------------------------------------
// Inline qidx decode: query_rels may be int64 or int32 (jax x64 config).
// If int64 LE with values < 4096, every high 32-bit word is 0. Sampling 64
// odd words (512 B — safe under both interpretations) distinguishes them.
// Executed by warp 0 only; result broadcast via shared.
// ---------------------------------------------------------------------------
__device__ __forceinline__ void decode_qidx_warp0(const void* qr, int b,
                                                  int t, int* s_qidx) {
    if (t < 32) {
        const int* p32 = (const int*)qr;
        int hi = p32[2 * t + 1] | p32[2 * (t + 32) + 1];
        bool is32 = __any_sync(0xFFFFFFFFu, hi != 0);
        if (t == 0) {
            *s_qidx = is32 ? p32[b] : (int)((const long long*)qr)[b];
        }
    }
}

// ---------------------------------------------------------------------------
// Kernel 1: fused copy + threshold detection (R7-proven shape: 256 threads,
// warp-per-row, 8 rows, flat body). Issue order is load -> STORE -> prologue:
// both the row LDG.128s AND the dependent STG.128s are issued before the
// decode/q-stage barriers (ptxas moves neither across BAR.SYNC), so the
// 2 KB/warp of store traffic drains while the prologue runs instead of
// waiting behind two syncs. Each warp holds the FULL q row in registers, so
// the query norm rides the existing shuffle reduction as a third
// accumulator. Lane 0 computes s = dot/(max(||r||,eps)*max(||q||,eps)) and
// bumps g_cnt[b] only when s clears the threshold (conservative margin;
// never taken for this data distribution -> zero global atomics on the
// common path). No sims array is stored: the tail's rare path recomputes.
// The PDL trigger lets the dependent tail grid become resident during the
// drain of our final wave.
// ---------------------------------------------------------------------------
__global__ void __launch_bounds__(256) fuse_copy_sims_kernel(
    const float* __restrict__ in, float* __restrict__ out,
    const void* __restrict__ qr, const float* __restrict__ thr_raw) {
    __shared__ float qs[DD];
    __shared__ int   s_qidx;

    int cta = blockIdx.x;
    int b = cta >> 9;            // 512 CTAs per batch
    int t = threadIdx.x;
    int warp = t >> 5;
    int lane = t & 31;
    size_t row = (size_t)cta * 8 + warp;

    // Hoisted scalar load (L2/const-hot); overlaps everything below.
    float traw = __ldg(thr_raw);

    // Issue the bulk-stream loads AND stores before the prologue barriers.
    const float4* rp = (const float4*)(in + row * DD);
    float4* op = (float4*)(out + row * DD);
    float4 a0 = __ldcs(rp + lane);
    float4 a1 = __ldcs(rp + lane + 32);
    __stcs(op + lane, a0);
    __stcs(op + lane + 32, a1);

    decode_qidx_warp0(qr, b, t, &s_qidx);
    __syncthreads();
    int qidx = s_qidx;

    // cooperative q stage: 256 threads, 256 floats (L2-hot)
    qs[t] = __ldg(in + ((size_t)b * RR + qidx) * DD + t);
    __syncthreads();

    float4 q0 = *(const float4*)(qs + 4 * lane);
    float4 q1 = *(const float4*)(qs + 128 + 4 * lane);

    float dot = a0.x * q0.x + a0.y * q0.y + a0.z * q0.z + a0.w * q0.w
              + a1.x * q1.x + a1.y * q1.y + a1.z * q1.z + a1.w * q1.w;
    float ss  = a0.x * a0.x + a0.y * a0.y + a0.z * a0.z + a0.w * a0.w
              + a1.x * a1.x + a1.y * a1.y + a1.z * a1.z + a1.w * a1.w;
    float qq  = q0.x * q0.x + q0.y * q0.y + q0.z * q0.z + q0.w * q0.w
              + q1.x * q1.x + q1.y * q1.y + q1.z * q1.z + q1.w * q1.w;

#pragma unroll
    for (int o = 16; o > 0; o >>= 1) {
        dot += __shfl_xor_sync(0xFFFFFFFFu, dot, o);
        ss  += __shfl_xor_sync(0xFFFFFFFFu, ss, o);
        qq  += __shfl_xor_sync(0xFFFFFFFFu, qq, o);
    }
    if (lane == 0) {
        float nrm = fmaxf(sqrtf(ss), 1e-12f);
        float qn  = fmaxf(sqrtf(qq), 1e-12f);
        float s = dot / (nrm * qn);
        if ((int)(row & (RR - 1)) == qidx) s = -1.0f;
        float thr = 1.0f / (1.0f + expf(-traw));
        if (s > thr - 1e-4f) atomicAdd(&g_cnt[b], 1);  // conservative; rare
    }

    // PDL: allow the dependent tail grid to launch/become resident now.
    cudaTriggerProgrammaticLaunchCompletion();
}

// Block reductions over 256 threads through shared `red`.
__device__ __forceinline__ float bred_sum(float v, float* red) {
    int t = threadIdx.x;
    red[t] = v;
    __syncthreads();
#pragma unroll
    for (int s = 128; s > 0; s >>= 1) {
        if (t < s) red[t] += red[t + s];
        __syncthreads();
    }
    float r = red[0];
    __syncthreads();
    return r;
}
__device__ __forceinline__ float bred_max(float v, float* red) {
    int t = threadIdx.x;
    red[t] = v;
    __syncthreads();
#pragma unroll
    for (int s = 128; s > 0; s >>= 1) {
        if (t < s) red[t] = fmaxf(red[t], red[t + s]);
        __syncthreads();
    }
    float r = red[0];
    __syncthreads();
    return r;
}

// ---------------------------------------------------------------------------
// Kernel 2: per-batch tail, launched with PDL. Common path: one load of
// g_cnt[b] -> exit (the copy already wrote the unchanged q row). Rare path:
// RECOMPUTE sims from `in` (read-only; ordering provided by
// cudaGridDependencySynchronize) warp-per-row into shared, exact recount
// (guards the conservative margin), masked softmax + coefficients +
// sparse weighted apply.
// ---------------------------------------------------------------------------
__global__ void __launch_bounds__(256) tail_kernel(
    const float* __restrict__ in, float* __restrict__ out,
    const void* __restrict__ qr,
    const float* __restrict__ thr_raw, const float* __restrict__ str_raw,
    const float* __restrict__ wscale,  const float* __restrict__ temp_p) {
    __shared__ float red[256];
    __shared__ float s_cf[RR];   // 16 KB
    __shared__ float qs[DD];
    __shared__ int   s_qidx;
    int b = blockIdx.x;
    int t = threadIdx.x;
    int warp = t >> 5;
    int lane = t & 31;

    // Wait for the copy grid's completion (memory fully visible).
    cudaGridDependencySynchronize();

    int cnt = g_cnt[b];
    __syncthreads();             // all reads done before t0 resets
    if (cnt == 0) return;        // common path: nothing to do
    if (t == 0) g_cnt[b] = 0;    // reset for next graph replay

    decode_qidx_warp0(qr, b, t, &s_qidx);
    __syncthreads();
    int qidx = s_qidx;

    // stage q and compute its norm
    qs[t] = in[((size_t)b * RR + qidx) * DD + t];
    __syncthreads();
    float qq_t = qs[t] * qs[t];
    float qsum = bred_sum(qq_t, red);
    float qn = fmaxf(sqrtf(qsum), 1e-12f);

    float4 q0 = *(const float4*)(qs + 4 * lane);
    float4 q1 = *(const float4*)(qs + 128 + 4 * lane);

    // recompute sims warp-per-row into shared
    for (int it = 0; it < RR / 8; it++) {
        int i = it * 8 + warp;
        const float4* rp = (const float4*)(in + ((size_t)b * RR + i) * DD);
        float4 c0 = rp[lane];
        float4 c1 = rp[lane + 32];
        float d2 = c0.x * q0.x + c0.y * q0.y + c0.z * q0.z + c0.w * q0.w
                 + c1.x * q1.x + c1.y * q1.y + c1.z * q1.z + c1.w * q1.w;
        float s2 = c0.x * c0.x + c0.y * c0.y + c0.z * c0.z + c0.w * c0.w
                 + c1.x * c1.x + c1.y * c1.y + c1.z * c1.z + c1.w * c1.w;
#pragma unroll
        for (int o = 16; o > 0; o >>= 1) {
            d2 += __shfl_xor_sync(0xFFFFFFFFu, d2, o);
            s2 += __shfl_xor_sync(0xFFFFFFFFu, s2, o);
        }
        if (lane == 0) {
            float nrm = fmaxf(sqrtf(s2), 1e-12f);
            float s = d2 / (nrm * qn);
            if (i == qidx) s = -1.0f;
            s_cf[i] = s;
        }
    }
    __syncthreads();

    float thr = 1.0f / (1.0f + expf(-thr_raw[0]));
    float strength = 0.2f / (1.0f + expf(-str_raw[0]));
    float ws = wscale[0];
    float temp = fminf(fmaxf(temp_p[0], 0.1f), 10.0f);

    // exact recount (guards the conservative margin)
    int lcnt = 0;
    for (int k = 0; k < 16; k++) {
        if (s_cf[t + k * 256] > thr) lcnt++;
    }
    int total = (int)bred_sum((float)lcnt, red);
    if (total == 0) return;      // margin-induced false positive: row is fine

    float lmax = -1e9f;
    for (int k = 0; k < 16; k++) {
        float s = s_cf[t + k * 256];
        if (s > thr) lmax = fmaxf(lmax, s / temp);
    }
    float m = bred_max(lmax, red);

    float lz = 0.0f;
    for (int k = 0; k < 16; k++) {
        float s = s_cf[t + k * 256];
        if (s > thr) lz += expf(s / temp - m);
        // unmasked entries: exp(-1e9) underflows to exactly 0 in fp32
    }
    float Z = bred_sum(lz, red);

    // coefficient pass: c = softmax * gate * (1 + ws*s); overwrite s_cf
    float lS = 0.0f;
    for (int k = 0; k < 16; k++) {
        int i = t + k * 256;
        float s = s_cf[i];
        float c = 0.0f;
        if (s > thr) {
            float sw = 1.0f / (1.0f + expf(-(s - thr) * 10.0f));
            float w = expf(s / temp - m) / Z;
            c = w * sw * (1.0f + ws * s);
            lS += c;
        }
        s_cf[i] = c;
    }
    float S = bred_sum(lS, red);
    float inv = strength / (S + 1e-8f);

    // sparse weighted sum; thread t = dim index
    float acc = 0.0f;
    for (int j = 0; j < RR; j++) {
        float cf = s_cf[j];
        if (cf != 0.0f) {
            acc += cf * in[((size_t)b * RR + j) * DD + t];
        }
    }

    float q = qs[t];
    out[((size_t)b * RR + qidx) * DD + t] = (1.0f - strength) * q + inv * acc;
}

// ---------------------------------------------------------------------------
extern "C" void kernel_launch(void* const* d_in, const int* in_sizes, int n_in,
                              void* d_out, int out_size) {
    const float* reps    = (const float*)d_in[0];
    const void*  qrels   = d_in[1];
    const float* thr_raw = (const float*)d_in[2];
    const float* str_raw = (const float*)d_in[3];
    const float* wscale  = (const float*)d_in[4];
    const float* temp_p  = (const float*)d_in[5];
    float* out = (float*)d_out;

    fuse_copy_sims_kernel<<<NROW / 8, 256>>>(reps, out, qrels, thr_raw);

    // Tail with Programmatic Dependent Launch: becomes resident while the
    // copy's final wave drains; ordering via cudaGridDependencySynchronize.
    cudaLaunchConfig_t cfg = {};
    cfg.gridDim = dim3(BB, 1, 1);
    cfg.blockDim = dim3(256, 1, 1);
    cfg.dynamicSmemBytes = 0;
    cfg.stream = 0;
    cudaLaunchAttribute attrs[1];
    attrs[0].id = cudaLaunchAttributeProgrammaticStreamSerialization;
    attrs[0].val.programmaticStreamSerializationAllowed = 1;
    cfg.attrs = attrs;
    cfg.numAttrs = 1;
    cudaLaunchKernelEx(&cfg, tail_kernel, reps, out, qrels,
                       thr_raw, str_raw, wscale, temp_p);
}

// round 14
// speedup vs baseline: 1.0251x; 1.0251x over previous
#include <cuda_runtime.h>
#include <math.h>
#include <stdint.h>

#define BB 128
#define RR 4096
#define DD 256
#define NROW (BB * RR)

// Static device scratch (no allocations allowed). g_cnt is zero-initialized
// at load and self-resetting (tail kernel resets it each run).
__device__ int g_cnt[BB];

// ---------------------------------------------------------------------------
// Inline qidx decode: query_rels may be int64 or int32 (jax x64 config).
// If int64 LE with values < 4096, every high 32-bit word is 0. Sampling 64
// odd words (512 B — safe under both interpretations) distinguishes them.
// Executed by warp 0 only; result broadcast via shared.
// ---------------------------------------------------------------------------
__device__ __forceinline__ void decode_qidx_warp0(const void* qr, int b,
                                                  int t, int* s_qidx) {
    if (t < 32) {
        const int* p32 = (const int*)qr;
        int hi = p32[2 * t + 1] | p32[2 * (t + 32) + 1];
        bool is32 = __any_sync(0xFFFFFFFFu, hi != 0);
        if (t == 0) {
            *s_qidx = is32 ? p32[b] : (int)((const long long*)qr)[b];
        }
    }
}

// ---------------------------------------------------------------------------
// Kernel 1: fused copy + threshold detection (R7/R11-proven shape: 256
// threads, warp-per-row, 8 rows, flat body). Issue order is LOAD ->
// prologue -> STORE: the row LDG.128s are issued before the decode/q-stage
// barriers (their ~600-cycle latency drains under the prologue, and warps
// reach BAR.SYNC immediately because nothing before the barrier consumes
// the load results); the dependent STG.128s come after, by which time the
// data has arrived. (R12 measured that store-before-barrier inverts this
// and costs ~4 us.) Each warp holds the FULL q row in registers, so the
// query norm rides the existing shuffle reduction as a third accumulator.
// Lane 0 computes s = dot/(max(||r||,eps)*max(||q||,eps)) and bumps
// g_cnt[b] only when s clears the threshold (conservative margin; never
// taken for this data distribution -> zero global atomics on the common
// path). No sims array is stored: the tail's rare path recomputes. The PDL
// trigger lets the dependent tail grid become resident during our drain.
// ---------------------------------------------------------------------------
__global__ void __launch_bounds__(256) fuse_copy_sims_kernel(
    const float* __restrict__ in, float* __restrict__ out,
    const void* __restrict__ qr, const float* __restrict__ thr_raw) {
    __shared__ float qs[DD];
    __shared__ int   s_qidx;

    int cta = blockIdx.x;
    int b = cta >> 9;            // 512 CTAs per batch
    int t = threadIdx.x;
    int warp = t >> 5;
    int lane = t & 31;
    size_t row = (size_t)cta * 8 + warp;

    // Issue the bulk-stream loads immediately (independent of prologue).
    const float4* rp = (const float4*)(in + row * DD);
    float4 a0 = __ldcs(rp + lane);
    float4 a1 = __ldcs(rp + lane + 32);

    decode_qidx_warp0(qr, b, t, &s_qidx);
    __syncthreads();
    int qidx = s_qidx;

    // cooperative q stage: 256 threads, 256 floats (L2-hot)
    qs[t] = __ldg(in + ((size_t)b * RR + qidx) * DD + t);
    __syncthreads();

    float4* op = (float4*)(out + row * DD);
    __stcs(op + lane, a0);
    __stcs(op + lane + 32, a1);

    float4 q0 = *(const float4*)(qs + 4 * lane);
    float4 q1 = *(const float4*)(qs + 128 + 4 * lane);

    float dot = a0.x * q0.x + a0.y * q0.y + a0.z * q0.z + a0.w * q0.w
              + a1.x * q1.x + a1.y * q1.y + a1.z * q1.z + a1.w * q1.w;
    float ss  = a0.x * a0.x + a0.y * a0.y + a0.z * a0.z + a0.w * a0.w
              + a1.x * a1.x + a1.y * a1.y + a1.z * a1.z + a1.w * a1.w;
    float qq  = q0.x * q0.x + q0.y * q0.y + q0.z * q0.z + q0.w * q0.w
              + q1.x * q1.x + q1.y * q1.y + q1.z * q1.z + q1.w * q1.w;

#pragma unroll
    for (int o = 16; o > 0; o >>= 1) {
        dot += __shfl_xor_sync(0xFFFFFFFFu, dot, o);
        ss  += __shfl_xor_sync(0xFFFFFFFFu, ss, o);
        qq  += __shfl_xor_sync(0xFFFFFFFFu, qq, o);
    }
    if (lane == 0) {
        float nrm = fmaxf(sqrtf(ss), 1e-12f);
        float qn  = fmaxf(sqrtf(qq), 1e-12f);
        float s = dot / (nrm * qn);
        if ((int)(row & (RR - 1)) == qidx) s = -1.0f;
        float thr = 1.0f / (1.0f + expf(-thr_raw[0]));
        if (s > thr - 1e-4f) atomicAdd(&g_cnt[b], 1);  // conservative; rare
    }

    // PDL: allow the dependent tail grid to launch/become resident now.
    cudaTriggerProgrammaticLaunchCompletion();
}

// Block reductions over 256 threads through shared `red`.
__device__ __forceinline__ float bred_sum(float v, float* red) {
    int t = threadIdx.x;
    red[t] = v;
    __syncthreads();
#pragma unroll
    for (int s = 128; s > 0; s >>= 1) {
        if (t < s) red[t] += red[t + s];
        __syncthreads();
    }
    float r = red[0];
    __syncthreads();
    return r;
}
__device__ __forceinline__ float bred_max(float v, float* red) {
    int t = threadIdx.x;
    red[t] = v;
    __syncthreads();
#pragma unroll
    for (int s = 128; s > 0; s >>= 1) {
        if (t < s) red[t] = fmaxf(red[t], red[t + s]);
        __syncthreads();
    }
    float r = red[0];
    __syncthreads();
    return r;
}

// ---------------------------------------------------------------------------
// Kernel 2: per-batch tail, launched with PDL. Common path: one load of
// g_cnt[b] -> exit (the copy already wrote the unchanged q row). Rare path:
// RECOMPUTE sims from `in` (read-only; ordering provided by
// cudaGridDependencySynchronize) warp-per-row into shared, exact recount
// (guards the conservative margin), masked softmax + coefficients +
// sparse weighted apply.
// ---------------------------------------------------------------------------
__global__ void __launch_bounds__(256) tail_kernel(
    const float* __restrict__ in, float* __restrict__ out,
    const void* __restrict__ qr,
    const float* __restrict__ thr_raw, const float* __restrict__ str_raw,
    const float* __restrict__ wscale,  const float* __restrict__ temp_p) {
    __shared__ float red[256];
    __shared__ float s_cf[RR];   // 16 KB
    __shared__ float qs[DD];
    __shared__ int   s_qidx;
    int b = blockIdx.x;
    int t = threadIdx.x;
    int warp = t >> 5;
    int lane = t & 31;

    // Wait for the copy grid's completion (memory fully visible).
    cudaGridDependencySynchronize();

    int cnt = g_cnt[b];
    __syncthreads();             // all reads done before t0 resets
    if (cnt == 0) return;        // common path: nothing to do
    if (t == 0) g_cnt[b] = 0;    // reset for next graph replay

    decode_qidx_warp0(qr, b, t, &s_qidx);
    __syncthreads();
    int qidx = s_qidx;

    // stage q and compute its norm
    qs[t] = in[((size_t)b * RR + qidx) * DD + t];
    __syncthreads();
    float qq_t = qs[t] * qs[t];
    float qsum = bred_sum(qq_t, red);
    float qn = fmaxf(sqrtf(qsum), 1e-12f);

    float4 q0 = *(const float4*)(qs + 4 * lane);
    float4 q1 = *(const float4*)(qs + 128 + 4 * lane);

    // recompute sims warp-per-row into shared
    for (int it = 0; it < RR / 8; it++) {
        int i = it * 8 + warp;
        const float4* rp = (const float4*)(in + ((size_t)b * RR + i) * DD);
        float4 c0 = rp[lane];
        float4 c1 = rp[lane + 32];
        float d2 = c0.x * q0.x + c0.y * q0.y + c0.z * q0.z + c0.w * q0.w
                 + c1.x * q1.x + c1.y * q1.y + c1.z * q1.z + c1.w * q1.w;
        float s2 = c0.x * c0.x + c0.y * c0.y + c0.z * c0.z + c0.w * c0.w
                 + c1.x * c1.x + c1.y * c1.y + c1.z * c1.z + c1.w * c1.w;
#pragma unroll
        for (int o = 16; o > 0; o >>= 1) {
            d2 += __shfl_xor_sync(0xFFFFFFFFu, d2, o);
            s2 += __shfl_xor_sync(0xFFFFFFFFu, s2, o);
        }
        if (lane == 0) {
            float nrm = fmaxf(sqrtf(s2), 1e-12f);
            float s = d2 / (nrm * qn);
            if (i == qidx) s = -1.0f;
            s_cf[i] = s;
        }
    }
    __syncthreads();

    float thr = 1.0f / (1.0f + expf(-thr_raw[0]));
    float strength = 0.2f / (1.0f + expf(-str_raw[0]));
    float ws = wscale[0];
    float temp = fminf(fmaxf(temp_p[0], 0.1f), 10.0f);

    // exact recount (guards the conservative margin)
    int lcnt = 0;
    for (int k = 0; k < 16; k++) {
        if (s_cf[t + k * 256] > thr) lcnt++;
    }
    int total = (int)bred_sum((float)lcnt, red);
    if (total == 0) return;      // margin-induced false positive: row is fine

    float lmax = -1e9f;
    for (int k = 0; k < 16; k++) {
        float s = s_cf[t + k * 256];
        if (s > thr) lmax = fmaxf(lmax, s / temp);
    }
    float m = bred_max(lmax, red);

    float lz = 0.0f;
    for (int k = 0; k < 16; k++) {
        float s = s_cf[t + k * 256];
        if (s > thr) lz += expf(s / temp - m);
        // unmasked entries: exp(-1e9) underflows to exactly 0 in fp32
    }
    float Z = bred_sum(lz, red);

    // coefficient pass: c = softmax * gate * (1 + ws*s); overwrite s_cf
    float lS = 0.0f;
    for (int k = 0; k < 16; k++) {
        int i = t + k * 256;
        float s = s_cf[i];
        float c = 0.0f;
        if (s > thr) {
            float sw = 1.0f / (1.0f + expf(-(s - thr) * 10.0f));
            float w = expf(s / temp - m) / Z;
            c = w * sw * (1.0f + ws * s);
            lS += c;
        }
        s_cf[i] = c;
    }
    float S = bred_sum(lS, red);
    float inv = strength / (S + 1e-8f);

    // sparse weighted sum; thread t = dim index
    float acc = 0.0f;
    for (int j = 0; j < RR; j++) {
        float cf = s_cf[j];
        if (cf != 0.0f) {
            acc += cf * in[((size_t)b * RR + j) * DD + t];
        }
    }

    float q = qs[t];
    out[((size_t)b * RR + qidx) * DD + t] = (1.0f - strength) * q + inv * acc;
}

// ---------------------------------------------------------------------------
extern "C" void kernel_launch(void* const* d_in, const int* in_sizes, int n_in,
                              void* d_out, int out_size) {
    const float* reps    = (const float*)d_in[0];
    const void*  qrels   = d_in[1];
    const float* thr_raw = (const float*)d_in[2];
    const float* str_raw = (const float*)d_in[3];
    const float* wscale  = (const float*)d_in[4];
    const float* temp_p  = (const float*)d_in[5];
    float* out = (float*)d_out;

    fuse_copy_sims_kernel<<<NROW / 8, 256>>>(reps, out, qrels, thr_raw);

    // Tail with Programmatic Dependent Launch: becomes resident while the
    // copy's final wave drains; ordering via cudaGridDependencySynchronize.
    cudaLaunchConfig_t cfg = {};
    cfg.gridDim = dim3(BB, 1, 1);
    cfg.blockDim = dim3(256, 1, 1);
    cfg.dynamicSmemBytes = 0;
    cfg.stream = 0;
    cudaLaunchAttribute attrs[1];
    attrs[0].id = cudaLaunchAttributeProgrammaticStreamSerialization;
    attrs[0].val.programmaticStreamSerializationAllowed = 1;
    cfg.attrs = attrs;
    cfg.numAttrs = 1;
    cudaLaunchKernelEx(&cfg, tail_kernel, reps, out, qrels,
                       thr_raw, str_raw, wscale, temp_p);
}